// round 2
// baseline (speedup 1.0000x reference)
#include <cuda_runtime.h>

#define B_   8
#define CIN  96
#define CMID 48
#define HH   256
#define WW   256
#define H2   128
#define W2   128
#define CO   192

// Scratch for conv1 output y = conv(x, w_body): (8, 48, 256, 256) fp32 = 100 MB.
__device__ float g_y[B_ * CMID * HH * WW];

// ---- packed f32x2 helpers (FFMA2 exists in SASS only via PTX fma.rn.f32x2) --
typedef unsigned long long ull;

__device__ __forceinline__ ull pk2(float lo, float hi) {
    ull r;
    asm("mov.b64 %0, {%1, %2};" : "=l"(r) : "f"(lo), "f"(hi));
    return r;
}
__device__ __forceinline__ ull splat2(float v) {
    ull r;
    asm("mov.b64 %0, {%1, %1};" : "=l"(r) : "f"(v));
    return r;
}
__device__ __forceinline__ void unpk2(float& lo, float& hi, ull v) {
    asm("mov.b64 {%0, %1}, %2;" : "=f"(lo), "=f"(hi) : "l"(v));
}
#define FMA2(acc, a, b) \
    asm("fma.rn.f32x2 %0, %1, %2, %0;" : "+l"(acc) : "l"(a), "l"(b))

// ---------------------------------------------------------------------------
// Kernel A: 3x3 conv, 96 -> 48 channels, pad 1, fp32 with packed FFMA2.
// CTA tile: 16 oc x 8 rows x 32 cols. Thread tile: 4 oc x 4 cols.
// Vector lane = oc pair (from sw float4 halves); x value splatted.
// ---------------------------------------------------------------------------
#define OCT 16
#define ICB 8

__global__ __launch_bounds__(256) void conv1_kernel(
    const float* __restrict__ x, const float* __restrict__ w)
{
    __shared__ __align__(16) float sx[ICB][10][36];   // [ic][row+halo][col+halo]
    __shared__ __align__(16) float sw[ICB][9][OCT];   // [ic][tap][oc_local]

    const int tid  = threadIdx.x;
    const int lane = tid & 31;
    const int wid  = tid >> 5;          // 0..7
    const int row  = wid;
    const int colg = lane >> 2;         // 0..7
    const int ocg  = lane & 3;          // 0..3
    const int col0 = colg * 4;

    const int w0c = blockIdx.x * 32;
    const int h0  = blockIdx.y * 8;
    const int b   = blockIdx.z / 3;
    const int ocb = blockIdx.z % 3;

    // acc2[p][q]: pixel p (0..3), q=0 -> oc pair (ocg*4+0, +1), q=1 -> (+2, +3)
    ull acc2[4][2];
    #pragma unroll
    for (int p = 0; p < 4; p++) { acc2[p][0] = 0ull; acc2[p][1] = 0ull; }

    for (int icc = 0; icc < CIN; icc += ICB) {
        // ---- load x tile (8 ic x 10 rows x 34 cols), coalesced by row ----
        for (int rr = wid; rr < ICB * 10; rr += 8) {
            int ic = rr / 10, r = rr % 10;
            int gr = h0 - 1 + r;
            const float* xrow = x + (((b * CIN + icc + ic) * HH + gr) * WW);
            bool rowok = ((unsigned)gr < (unsigned)HH);
            int gc = w0c - 1 + lane;
            sx[ic][r][lane] = (rowok && (unsigned)gc < (unsigned)WW) ? xrow[gc] : 0.f;
            if (lane < 2) {
                int gc2 = w0c + 31 + lane;
                sx[ic][r][32 + lane] =
                    (rowok && (unsigned)gc2 < (unsigned)WW) ? xrow[gc2] : 0.f;
            }
        }
        // ---- load weight chunk: sw[ic][tap][oc_local] ----
        for (int idx = tid; idx < ICB * 9 * OCT; idx += 256) {
            int ic  = idx / (9 * OCT);
            int rem = idx % (9 * OCT);
            int tap = rem / OCT;
            int ocl = rem % OCT;
            sw[ic][tap][ocl] = w[((ocb * OCT + ocl) * CIN + icc + ic) * 9 + tap];
        }
        __syncthreads();

        #pragma unroll
        for (int ic = 0; ic < ICB; ic++) {
            #pragma unroll
            for (int kh = 0; kh < 3; kh++) {
                float4 xa = *(const float4*)&sx[ic][row + kh][col0];
                float4 xb = *(const float4*)&sx[ic][row + kh][col0 + 4];
                ull xs[6];
                xs[0] = splat2(xa.x); xs[1] = splat2(xa.y);
                xs[2] = splat2(xa.z); xs[3] = splat2(xa.w);
                xs[4] = splat2(xb.x); xs[5] = splat2(xb.y);
                #pragma unroll
                for (int kw = 0; kw < 3; kw++) {
                    float4 wv = *(const float4*)&sw[ic][kh * 3 + kw][ocg * 4];
                    ull w01 = pk2(wv.x, wv.y);
                    ull w23 = pk2(wv.z, wv.w);
                    #pragma unroll
                    for (int p = 0; p < 4; p++) {
                        FMA2(acc2[p][0], xs[kw + p], w01);
                        FMA2(acc2[p][1], xs[kw + p], w23);
                    }
                }
            }
        }
        __syncthreads();
    }

    // ---- unpack and store (float4 over pixels, per oc) ----
    float acc[4][4];  // [o][p]
    #pragma unroll
    for (int p = 0; p < 4; p++) {
        unpk2(acc[0][p], acc[1][p], acc2[p][0]);
        unpk2(acc[2][p], acc[3][p], acc2[p][1]);
    }
    #pragma unroll
    for (int o = 0; o < 4; o++) {
        int oc = ocb * OCT + ocg * 4 + o;
        float4 v = make_float4(acc[o][0], acc[o][1], acc[o][2], acc[o][3]);
        *(float4*)&g_y[((b * CMID + oc) * HH + (h0 + row)) * WW + w0c + col0] = v;
    }
}

// ---------------------------------------------------------------------------
// Kernel B: fused pixel_unshuffle + mask interleave + grouped 3x3 conv.
// (unchanged from round 1; 74us, DRAM-limited tail)
// ---------------------------------------------------------------------------
__global__ __launch_bounds__(256) void conv2_kernel(
    const float* __restrict__ mask, const float* __restrict__ wp,
    float* __restrict__ out)
{
    __shared__ __align__(16) float sy[2][10][132];
    __shared__ __align__(16) float smm[2][10][132];
    __shared__ float swp[36];

    const int tid = threadIdx.x;
    const int hb  = blockIdx.x * 8;
    const int gp  = blockIdx.y;     // 0..95 : (c, dy)
    const int b   = blockIdx.z;
    const int c   = gp >> 1;
    const int dy  = gp & 1;
    const int g0  = 4 * c + 2 * dy;

    if (tid < 36) swp[tid] = wp[g0 * 18 + tid];

    for (int idx = tid; idx < 10 * 128; idx += 256) {
        int r = idx >> 7;
        int q = idx & 127;
        int gy = 2 * (hb - 1 + r) + dy;
        float2 yv = make_float2(0.f, 0.f);
        float2 mv = make_float2(0.f, 0.f);
        if ((unsigned)gy < (unsigned)HH) {
            yv = *(const float2*)&g_y[(((b * CMID + c) * HH + gy) * WW) + 2 * q];
            mv = *(const float2*)&mask[((b * HH + gy) * WW) + 2 * q];
        }
        sy[0][r][1 + q] = yv.x;  sy[1][r][1 + q] = yv.y;
        smm[0][r][1 + q] = mv.x; smm[1][r][1 + q] = mv.y;
    }
    if (tid < 10) {
        sy[0][tid][0] = 0.f;   sy[1][tid][0] = 0.f;
        sy[0][tid][129] = 0.f; sy[1][tid][129] = 0.f;
        smm[0][tid][0] = 0.f;   smm[1][tid][0] = 0.f;
        smm[0][tid][129] = 0.f; smm[1][tid][129] = 0.f;
    }
    __syncthreads();

    const int hr = tid >> 5;
    const int wq = tid & 31;
    const int w0 = wq * 4;

    float a0[4] = {0.f, 0.f, 0.f, 0.f};
    float a1[4] = {0.f, 0.f, 0.f, 0.f};

    #pragma unroll
    for (int kh = 0; kh < 3; kh++) {
        int r = hr + kh;
        float4 y0a = *(const float4*)&sy[0][r][w0];
        float2 y0b = *(const float2*)&sy[0][r][w0 + 4];
        float4 y1a = *(const float4*)&sy[1][r][w0];
        float2 y1b = *(const float2*)&sy[1][r][w0 + 4];
        float4 m0a = *(const float4*)&smm[0][r][w0];
        float2 m0b = *(const float2*)&smm[0][r][w0 + 4];
        float4 m1a = *(const float4*)&smm[1][r][w0];
        float2 m1b = *(const float2*)&smm[1][r][w0 + 4];
        float yv0[6] = {y0a.x, y0a.y, y0a.z, y0a.w, y0b.x, y0b.y};
        float yv1[6] = {y1a.x, y1a.y, y1a.z, y1a.w, y1b.x, y1b.y};
        float mv0[6] = {m0a.x, m0a.y, m0a.z, m0a.w, m0b.x, m0b.y};
        float mv1[6] = {m1a.x, m1a.y, m1a.z, m1a.w, m1b.x, m1b.y};
        #pragma unroll
        for (int kw = 0; kw < 3; kw++) {
            float wy0 = swp[kh * 3 + kw];
            float wm0 = swp[9 + kh * 3 + kw];
            float wy1 = swp[18 + kh * 3 + kw];
            float wm1 = swp[27 + kh * 3 + kw];
            #pragma unroll
            for (int p = 0; p < 4; p++) {
                a0[p] = fmaf(wy0, yv0[kw + p], a0[p]);
                a0[p] = fmaf(wm0, mv0[kw + p], a0[p]);
                a1[p] = fmaf(wy1, yv1[kw + p], a1[p]);
                a1[p] = fmaf(wm1, mv1[kw + p], a1[p]);
            }
        }
    }

    const int h = hb + hr;
    *(float4*)&out[((b * CO + g0) * H2 + h) * W2 + w0] =
        make_float4(a0[0], a0[1], a0[2], a0[3]);
    *(float4*)&out[((b * CO + g0 + 1) * H2 + h) * W2 + w0] =
        make_float4(a1[0], a1[1], a1[2], a1[3]);
}

// ---------------------------------------------------------------------------
extern "C" void kernel_launch(void* const* d_in, const int* in_sizes, int n_in,
                              void* d_out, int out_size)
{
    const float* x      = (const float*)d_in[0];
    const float* mask   = (const float*)d_in[1];
    const float* w_body = (const float*)d_in[2];
    const float* w_proj = (const float*)d_in[3];
    float* out = (float*)d_out;

    dim3 gA(WW / 32, HH / 8, B_ * 3);   // (8, 32, 24)
    conv1_kernel<<<gA, 256>>>(x, w_body);

    dim3 gB(H2 / 8, 96, B_);            // (16, 96, 8)
    conv2_kernel<<<gB, 256>>>(mask, w_proj, out);
}

// round 4
// speedup vs baseline: 2.3815x; 2.3815x over previous
#include <cuda_runtime.h>
#include <cstdint>

#define B_   8
#define CIN  96
#define CMID 48
#define HH   256
#define WW   256
#define H2   128
#define W2   128
#define CO   192

// conv1 output y: (8, 48, 256, 256) fp32 = 100 MB scratch.
__device__ float g_y[B_ * CMID * HH * WW];
// Pre-converted tf32 weights: [chunk12][tap9][icl8][oc48]
__device__ unsigned g_wp[12 * 9 * 8 * 48];

__device__ __forceinline__ unsigned f2tf32(float v) {
    unsigned t;
    asm("cvt.rna.tf32.f32 %0, %1;" : "=r"(t) : "f"(v));
    return t;
}

__device__ __forceinline__ void mma_tf32(float* c,
    unsigned a0, unsigned a1, unsigned a2, unsigned a3,
    unsigned b0, unsigned b1)
{
    asm volatile(
        "mma.sync.aligned.m16n8k8.row.col.f32.tf32.tf32.f32 "
        "{%0,%1,%2,%3}, {%4,%5,%6,%7}, {%8,%9}, {%0,%1,%2,%3};"
        : "+f"(c[0]), "+f"(c[1]), "+f"(c[2]), "+f"(c[3])
        : "r"(a0), "r"(a1), "r"(a2), "r"(a3), "r"(b0), "r"(b1));
}

// ---------------------------------------------------------------------------
// Prepass: w_body[oc48][ic96][tap9] -> g_wp[chunk][tap][icl][oc] (tf32 bits)
// ---------------------------------------------------------------------------
__global__ void prep_w_kernel(const float* __restrict__ w)
{
    int i = blockIdx.x * 256 + threadIdx.x;
    if (i >= 12 * 9 * 8 * 48) return;
    int chunk = i / 3456;
    int r  = i % 3456;
    int tap = r / 384;
    int r2  = r % 384;
    int icl = r2 / 48;
    int oc  = r2 % 48;
    int ic  = chunk * 8 + icl;
    g_wp[i] = f2tf32(w[(oc * 96 + ic) * 9 + tap]);
}

// ---------------------------------------------------------------------------
// conv1 via mma.sync tf32 implicit GEMM.
// CTA: 256 thr / 8 warps. Tile: 512 pixels (4 rows x 128 cols) x 48 oc.
// Warp w: 64 consecutive pixels (row w>>1, colbase (w&1)*64), 4 m-tiles of 16.
// K = 12 chunks (8 ic) x 9 taps, one m16n8k8 k-step per (chunk, tap).
// ---------------------------------------------------------------------------
__global__ __launch_bounds__(256) void conv1_mma_kernel(
    const float* __restrict__ x)
{
    __shared__ unsigned xs[8][6][132];   // [icl][row(+halo2)][col(+halo, pad)]
    __shared__ unsigned wsm[9][8][56];   // [tap][icl][oc pad56]

    const int tid  = threadIdx.x;
    const int lane = tid & 31;
    const int wid  = tid >> 5;
    const int g    = lane >> 2;   // group id
    const int u    = lane & 3;    // thread-in-group

    const int w0 = blockIdx.x * 128;
    const int h0 = blockIdx.y * 4;
    const int b  = blockIdx.z;

    const int wrow  = wid >> 1;        // pixel row within CTA (0..3)
    const int wcolb = (wid & 1) * 64;  // pixel col base within 128

    float acc[4][6][4];
    #pragma unroll
    for (int t = 0; t < 4; t++)
        #pragma unroll
        for (int n = 0; n < 6; n++)
            #pragma unroll
            for (int k = 0; k < 4; k++)
                acc[t][n][k] = 0.f;

    for (int chunk = 0; chunk < 12; chunk++) {
        // ---- stage x: 8 ic x 6 rows x 132 cols, tf32, zero-padded ----
        for (int rb = wid; rb < 48; rb += 8) {
            int ic = rb / 6, r = rb % 6;
            int gr = h0 - 1 + r;
            const float* src =
                x + ((size_t)((b * CIN + chunk * 8 + ic) * HH + gr)) * WW;
            bool rok = ((unsigned)gr < (unsigned)HH);
            for (int c = lane; c < 132; c += 32) {
                int gc = w0 - 1 + c;
                float v = (rok && (unsigned)gc < (unsigned)WW) ? src[gc] : 0.f;
                xs[ic][r][c] = f2tf32(v);
            }
        }
        // ---- stage weights: [tap][icl][oc] pitch 56 ----
        for (int j = tid; j < 3456; j += 256) {
            int tap = j / 384;
            int r2  = j % 384;
            int icl = r2 / 48;
            int oc  = r2 % 48;
            wsm[tap][icl][oc] = g_wp[chunk * 3456 + j];
        }
        __syncthreads();

        #pragma unroll
        for (int tap = 0; tap < 9; tap++) {
            const int kh = tap / 3, kw = tap % 3;
            const int xr = wrow + kh;

            unsigned bf[6][2];
            #pragma unroll
            for (int n = 0; n < 6; n++) {
                bf[n][0] = wsm[tap][u][n * 8 + g];
                bf[n][1] = wsm[tap][u + 4][n * 8 + g];
            }
            #pragma unroll
            for (int t = 0; t < 4; t++) {
                const int colc = wcolb + t * 16 + g + kw;
                unsigned a0 = xs[u][xr][colc];
                unsigned a1 = xs[u][xr][colc + 8];
                unsigned a2 = xs[u + 4][xr][colc];
                unsigned a3 = xs[u + 4][xr][colc + 8];
                #pragma unroll
                for (int n = 0; n < 6; n++)
                    mma_tf32(acc[t][n], a0, a1, a2, a3, bf[n][0], bf[n][1]);
            }
        }
        __syncthreads();
    }

    // ---- store D: c0=(p, oc), c1=(p, oc+1), c2=(p+8, oc), c3=(p+8, oc+1) ----
    #pragma unroll
    for (int t = 0; t < 4; t++) {
        const int p0 = wid * 64 + t * 16 + g;        // pixel for c0/c1
        const int h  = h0 + (p0 >> 7);
        const int wc = w0 + (p0 & 127);
        #pragma unroll
        for (int n = 0; n < 6; n++) {
            const int oc = n * 8 + 2 * u;
            float* base = g_y + ((size_t)(b * CMID + oc) * HH + h) * WW + wc;
            base[0]         = acc[t][n][0];
            base[HH * WW]   = acc[t][n][1];
            base[8]         = acc[t][n][2];
            base[HH * WW + 8] = acc[t][n][3];
        }
    }
}

// ---------------------------------------------------------------------------
// Kernel B: fused pixel_unshuffle + mask interleave + grouped 3x3 conv.
// (unchanged; ~74us)
// ---------------------------------------------------------------------------
__global__ __launch_bounds__(256) void conv2_kernel(
    const float* __restrict__ mask, const float* __restrict__ wp,
    float* __restrict__ out)
{
    __shared__ __align__(16) float sy[2][10][132];
    __shared__ __align__(16) float smm[2][10][132];
    __shared__ float swp[36];

    const int tid = threadIdx.x;
    const int hb  = blockIdx.x * 8;
    const int gp  = blockIdx.y;
    const int b   = blockIdx.z;
    const int c   = gp >> 1;
    const int dy  = gp & 1;
    const int g0  = 4 * c + 2 * dy;

    if (tid < 36) swp[tid] = wp[g0 * 18 + tid];

    for (int idx = tid; idx < 10 * 128; idx += 256) {
        int r = idx >> 7;
        int q = idx & 127;
        int gy = 2 * (hb - 1 + r) + dy;
        float2 yv = make_float2(0.f, 0.f);
        float2 mv = make_float2(0.f, 0.f);
        if ((unsigned)gy < (unsigned)HH) {
            yv = *(const float2*)&g_y[(((b * CMID + c) * HH + gy) * WW) + 2 * q];
            mv = *(const float2*)&mask[((b * HH + gy) * WW) + 2 * q];
        }
        sy[0][r][1 + q] = yv.x;  sy[1][r][1 + q] = yv.y;
        smm[0][r][1 + q] = mv.x; smm[1][r][1 + q] = mv.y;
    }
    if (tid < 10) {
        sy[0][tid][0] = 0.f;   sy[1][tid][0] = 0.f;
        sy[0][tid][129] = 0.f; sy[1][tid][129] = 0.f;
        smm[0][tid][0] = 0.f;   smm[1][tid][0] = 0.f;
        smm[0][tid][129] = 0.f; smm[1][tid][129] = 0.f;
    }
    __syncthreads();

    const int hr = tid >> 5;
    const int wq = tid & 31;
    const int w0 = wq * 4;

    float a0[4] = {0.f, 0.f, 0.f, 0.f};
    float a1[4] = {0.f, 0.f, 0.f, 0.f};

    #pragma unroll
    for (int kh = 0; kh < 3; kh++) {
        int r = hr + kh;
        float4 y0a = *(const float4*)&sy[0][r][w0];
        float2 y0b = *(const float2*)&sy[0][r][w0 + 4];
        float4 y1a = *(const float4*)&sy[1][r][w0];
        float2 y1b = *(const float2*)&sy[1][r][w0 + 4];
        float4 m0a = *(const float4*)&smm[0][r][w0];
        float2 m0b = *(const float2*)&smm[0][r][w0 + 4];
        float4 m1a = *(const float4*)&smm[1][r][w0];
        float2 m1b = *(const float2*)&smm[1][r][w0 + 4];
        float yv0[6] = {y0a.x, y0a.y, y0a.z, y0a.w, y0b.x, y0b.y};
        float yv1[6] = {y1a.x, y1a.y, y1a.z, y1a.w, y1b.x, y1b.y};
        float mv0[6] = {m0a.x, m0a.y, m0a.z, m0a.w, m0b.x, m0b.y};
        float mv1[6] = {m1a.x, m1a.y, m1a.z, m1a.w, m1b.x, m1b.y};
        #pragma unroll
        for (int kw = 0; kw < 3; kw++) {
            float wy0 = swp[kh * 3 + kw];
            float wm0 = swp[9 + kh * 3 + kw];
            float wy1 = swp[18 + kh * 3 + kw];
            float wm1 = swp[27 + kh * 3 + kw];
            #pragma unroll
            for (int p = 0; p < 4; p++) {
                a0[p] = fmaf(wy0, yv0[kw + p], a0[p]);
                a0[p] = fmaf(wm0, mv0[kw + p], a0[p]);
                a1[p] = fmaf(wy1, yv1[kw + p], a1[p]);
                a1[p] = fmaf(wm1, mv1[kw + p], a1[p]);
            }
        }
    }

    const int h = hb + hr;
    *(float4*)&out[((b * CO + g0) * H2 + h) * W2 + w0] =
        make_float4(a0[0], a0[1], a0[2], a0[3]);
    *(float4*)&out[((b * CO + g0 + 1) * H2 + h) * W2 + w0] =
        make_float4(a1[0], a1[1], a1[2], a1[3]);
}

// ---------------------------------------------------------------------------
extern "C" void kernel_launch(void* const* d_in, const int* in_sizes, int n_in,
                              void* d_out, int out_size)
{
    const float* x      = (const float*)d_in[0];
    const float* mask   = (const float*)d_in[1];
    const float* w_body = (const float*)d_in[2];
    const float* w_proj = (const float*)d_in[3];
    float* out = (float*)d_out;

    prep_w_kernel<<<(12 * 9 * 8 * 48 + 255) / 256, 256>>>(w_body);

    dim3 g1(WW / 128, HH / 4, B_);      // (2, 64, 8) = 1024 CTAs
    conv1_mma_kernel<<<g1, 256>>>(x);

    dim3 g2(H2 / 8, 96, B_);            // (16, 96, 8)
    conv2_kernel<<<g2, 256>>>(mask, w_proj, out);
}

// round 5
// speedup vs baseline: 3.8512x; 1.6171x over previous
#include <cuda_runtime.h>
#include <cstdint>

#define B_   8
#define CIN  96
#define CMID 48
#define HH   256
#define WW   256
#define H2   128
#define W2   128
#define CO   192

// conv1 output y: (8, 48, 256, 256) fp32 = 100 MB scratch.
__device__ float g_y[B_ * CMID * HH * WW];
// Pre-packed fp16 weights: [chunk6][tap9][icp8][oc48] half2 (lo = even ic)
__device__ unsigned g_wph[6 * 9 * 8 * 48];

__device__ __forceinline__ unsigned pack_h2(float lo, float hi) {
    unsigned r;
    asm("{ .reg .b16 l, h; cvt.rn.f16.f32 l, %1; cvt.rn.f16.f32 h, %2; "
        "mov.b32 %0, {l, h}; }" : "=r"(r) : "f"(lo), "f"(hi));
    return r;
}

__device__ __forceinline__ void mma_f16(float* c,
    unsigned a0, unsigned a1, unsigned a2, unsigned a3,
    unsigned b0, unsigned b1)
{
    asm volatile(
        "mma.sync.aligned.m16n8k16.row.col.f32.f16.f16.f32 "
        "{%0,%1,%2,%3}, {%4,%5,%6,%7}, {%8,%9}, {%0,%1,%2,%3};"
        : "+f"(c[0]), "+f"(c[1]), "+f"(c[2]), "+f"(c[3])
        : "r"(a0), "r"(a1), "r"(a2), "r"(a3), "r"(b0), "r"(b1));
}

// ---------------------------------------------------------------------------
// Prepass: w_body[oc48][ic96][tap9] -> g_wph[chunk][tap][icp][oc] (half2)
// ---------------------------------------------------------------------------
__global__ void prep_w_kernel(const float* __restrict__ w)
{
    int i = blockIdx.x * 256 + threadIdx.x;
    if (i >= 6 * 9 * 8 * 48) return;
    int chunk = i / 3456;
    int r  = i % 3456;
    int tap = r / 384;
    int r2  = r % 384;
    int icp = r2 / 48;
    int oc  = r2 % 48;
    int ic  = chunk * 16 + icp * 2;
    g_wph[i] = pack_h2(w[(oc * 96 + ic) * 9 + tap],
                       w[(oc * 96 + ic + 1) * 9 + tap]);
}

// ---------------------------------------------------------------------------
// conv1 via mma.sync fp16 m16n8k16 implicit GEMM.
// CTA: 256 thr / 8 warps. Tile: 512 pixels (4 rows x 128 cols) x 48 oc.
// K = 6 chunks (16 ic as 8 half2-pairs) x 9 taps.
// ---------------------------------------------------------------------------
__global__ __launch_bounds__(256) void conv1_mma_kernel(
    const float* __restrict__ x)
{
    __shared__ unsigned xs[8][6][132];   // [icp][row(+halo2)][col(+halo)] half2
    __shared__ unsigned wsm[9][8][56];   // [tap][icp][oc pad56] half2

    const int tid  = threadIdx.x;
    const int lane = tid & 31;
    const int wid  = tid >> 5;
    const int g    = lane >> 2;   // group id (0..7)
    const int u    = lane & 3;    // thread-in-group (0..3)

    const int w0 = blockIdx.x * 128;
    const int h0 = blockIdx.y * 4;
    const int b  = blockIdx.z;

    const int wrow  = wid >> 1;        // pixel row within CTA (0..3)
    const int wcolb = (wid & 1) * 64;  // pixel col base within 128

    float acc[4][6][4];
    #pragma unroll
    for (int t = 0; t < 4; t++)
        #pragma unroll
        for (int n = 0; n < 6; n++)
            #pragma unroll
            for (int k = 0; k < 4; k++)
                acc[t][n][k] = 0.f;

    for (int chunk = 0; chunk < 6; chunk++) {
        // ---- stage x: 8 ic-pairs x 6 rows x 132 cols, half2, zero-padded ----
        for (int rb = wid; rb < 48; rb += 8) {
            int icp = rb / 6, r = rb % 6;
            int gr = h0 - 1 + r;
            const float* s0 =
                x + ((size_t)((b * CIN + chunk * 16 + icp * 2) * HH + gr)) * WW;
            const float* s1 = s0 + (size_t)HH * WW;
            bool rok = ((unsigned)gr < (unsigned)HH);
            for (int c = lane; c < 132; c += 32) {
                int gc = w0 - 1 + c;
                bool ok = rok && (unsigned)gc < (unsigned)WW;
                float v0 = ok ? s0[gc] : 0.f;
                float v1 = ok ? s1[gc] : 0.f;
                xs[icp][r][c] = pack_h2(v0, v1);
            }
        }
        // ---- stage weights: [tap][icp][oc] pitch 56 ----
        for (int j = tid; j < 3456; j += 256) {
            int tap = j / 384;
            int r2  = j % 384;
            int icp = r2 / 48;
            int oc  = r2 % 48;
            wsm[tap][icp][oc] = g_wph[chunk * 3456 + j];
        }
        __syncthreads();

        #pragma unroll
        for (int tap = 0; tap < 9; tap++) {
            const int kh = tap / 3, kw = tap % 3;
            const int xr = wrow + kh;

            unsigned bf[6][2];
            #pragma unroll
            for (int n = 0; n < 6; n++) {
                bf[n][0] = wsm[tap][u][n * 8 + g];       // k pairs 2u,2u+1
                bf[n][1] = wsm[tap][u + 4][n * 8 + g];   // k pairs 2u+8,2u+9
            }
            #pragma unroll
            for (int t = 0; t < 4; t++) {
                const int colc = wcolb + t * 16 + g + kw;
                unsigned a0 = xs[u][xr][colc];        // (row g,   k 2u..)
                unsigned a1 = xs[u][xr][colc + 8];    // (row g+8, k 2u..)
                unsigned a2 = xs[u + 4][xr][colc];    // (row g,   k 2u+8..)
                unsigned a3 = xs[u + 4][xr][colc + 8];// (row g+8, k 2u+8..)
                #pragma unroll
                for (int n = 0; n < 6; n++)
                    mma_f16(acc[t][n], a0, a1, a2, a3, bf[n][0], bf[n][1]);
            }
        }
        __syncthreads();
    }

    // ---- store D: c0=(p, oc), c1=(p, oc+1), c2=(p+8, oc), c3=(p+8, oc+1) ----
    #pragma unroll
    for (int t = 0; t < 4; t++) {
        const int p0 = wid * 64 + t * 16 + g;
        const int h  = h0 + (p0 >> 7);
        const int wc = w0 + (p0 & 127);
        #pragma unroll
        for (int n = 0; n < 6; n++) {
            const int oc = n * 8 + 2 * u;
            float* base = g_y + ((size_t)(b * CMID + oc) * HH + h) * WW + wc;
            base[0]           = acc[t][n][0];
            base[HH * WW]     = acc[t][n][1];
            base[8]           = acc[t][n][2];
            base[HH * WW + 8] = acc[t][n][3];
        }
    }
}

// ---------------------------------------------------------------------------
// Kernel B: fused pixel_unshuffle + mask interleave + grouped 3x3 conv.
// (unchanged; ~74us)
// ---------------------------------------------------------------------------
__global__ __launch_bounds__(256) void conv2_kernel(
    const float* __restrict__ mask, const float* __restrict__ wp,
    float* __restrict__ out)
{
    __shared__ __align__(16) float sy[2][10][132];
    __shared__ __align__(16) float smm[2][10][132];
    __shared__ float swp[36];

    const int tid = threadIdx.x;
    const int hb  = blockIdx.x * 8;
    const int gp  = blockIdx.y;
    const int b   = blockIdx.z;
    const int c   = gp >> 1;
    const int dy  = gp & 1;
    const int g0  = 4 * c + 2 * dy;

    if (tid < 36) swp[tid] = wp[g0 * 18 + tid];

    for (int idx = tid; idx < 10 * 128; idx += 256) {
        int r = idx >> 7;
        int q = idx & 127;
        int gy = 2 * (hb - 1 + r) + dy;
        float2 yv = make_float2(0.f, 0.f);
        float2 mv = make_float2(0.f, 0.f);
        if ((unsigned)gy < (unsigned)HH) {
            yv = *(const float2*)&g_y[(((b * CMID + c) * HH + gy) * WW) + 2 * q];
            mv = *(const float2*)&mask[((b * HH + gy) * WW) + 2 * q];
        }
        sy[0][r][1 + q] = yv.x;  sy[1][r][1 + q] = yv.y;
        smm[0][r][1 + q] = mv.x; smm[1][r][1 + q] = mv.y;
    }
    if (tid < 10) {
        sy[0][tid][0] = 0.f;   sy[1][tid][0] = 0.f;
        sy[0][tid][129] = 0.f; sy[1][tid][129] = 0.f;
        smm[0][tid][0] = 0.f;   smm[1][tid][0] = 0.f;
        smm[0][tid][129] = 0.f; smm[1][tid][129] = 0.f;
    }
    __syncthreads();

    const int hr = tid >> 5;
    const int wq = tid & 31;
    const int w0 = wq * 4;

    float a0[4] = {0.f, 0.f, 0.f, 0.f};
    float a1[4] = {0.f, 0.f, 0.f, 0.f};

    #pragma unroll
    for (int kh = 0; kh < 3; kh++) {
        int r = hr + kh;
        float4 y0a = *(const float4*)&sy[0][r][w0];
        float2 y0b = *(const float2*)&sy[0][r][w0 + 4];
        float4 y1a = *(const float4*)&sy[1][r][w0];
        float2 y1b = *(const float2*)&sy[1][r][w0 + 4];
        float4 m0a = *(const float4*)&smm[0][r][w0];
        float2 m0b = *(const float2*)&smm[0][r][w0 + 4];
        float4 m1a = *(const float4*)&smm[1][r][w0];
        float2 m1b = *(const float2*)&smm[1][r][w0 + 4];
        float yv0[6] = {y0a.x, y0a.y, y0a.z, y0a.w, y0b.x, y0b.y};
        float yv1[6] = {y1a.x, y1a.y, y1a.z, y1a.w, y1b.x, y1b.y};
        float mv0[6] = {m0a.x, m0a.y, m0a.z, m0a.w, m0b.x, m0b.y};
        float mv1[6] = {m1a.x, m1a.y, m1a.z, m1a.w, m1b.x, m1b.y};
        #pragma unroll
        for (int kw = 0; kw < 3; kw++) {
            float wy0 = swp[kh * 3 + kw];
            float wm0 = swp[9 + kh * 3 + kw];
            float wy1 = swp[18 + kh * 3 + kw];
            float wm1 = swp[27 + kh * 3 + kw];
            #pragma unroll
            for (int p = 0; p < 4; p++) {
                a0[p] = fmaf(wy0, yv0[kw + p], a0[p]);
                a0[p] = fmaf(wm0, mv0[kw + p], a0[p]);
                a1[p] = fmaf(wy1, yv1[kw + p], a1[p]);
                a1[p] = fmaf(wm1, mv1[kw + p], a1[p]);
            }
        }
    }

    const int h = hb + hr;
    *(float4*)&out[((b * CO + g0) * H2 + h) * W2 + w0] =
        make_float4(a0[0], a0[1], a0[2], a0[3]);
    *(float4*)&out[((b * CO + g0 + 1) * H2 + h) * W2 + w0] =
        make_float4(a1[0], a1[1], a1[2], a1[3]);
}

// ---------------------------------------------------------------------------
extern "C" void kernel_launch(void* const* d_in, const int* in_sizes, int n_in,
                              void* d_out, int out_size)
{
    const float* x      = (const float*)d_in[0];
    const float* mask   = (const float*)d_in[1];
    const float* w_body = (const float*)d_in[2];
    const float* w_proj = (const float*)d_in[3];
    float* out = (float*)d_out;

    prep_w_kernel<<<(6 * 9 * 8 * 48 + 255) / 256, 256>>>(w_body);

    dim3 g1(WW / 128, HH / 4, B_);      // (2, 64, 8) = 1024 CTAs
    conv1_mma_kernel<<<g1, 256>>>(x);

    dim3 g2(H2 / 8, 96, B_);            // (16, 96, 8)
    conv2_kernel<<<g2, 256>>>(mask, w_proj, out);
}

// round 6
// speedup vs baseline: 8.0785x; 2.0977x over previous
#include <cuda_runtime.h>
#include <cstdint>

#define B_   8
#define CIN  96
#define CMID 48
#define HH   256
#define WW   256
#define H2   128
#define W2   128
#define CO   192

// conv1 output y: (8, 48, 256, 256) fp32 = 100 MB scratch.
__device__ float g_y[B_ * CMID * HH * WW];
// Pre-packed fp16 weights: [chunk6][tap9][icp8][oc48] half2 (lo = even ic)
__device__ unsigned g_wph[6 * 9 * 8 * 48];
// Pre-packed, pre-padded fp16 x: [b][icp48][row 258][col 264] half2,
// row r <-> h = r-1, col c <-> w = c-1, borders zero. ~105 MB.
#define XPR 258
#define XPC 264
__device__ unsigned g_xh[B_ * 48 * XPR * XPC];

__device__ __forceinline__ unsigned pack_h2(float lo, float hi) {
    unsigned r;
    asm("{ .reg .b16 l, h; cvt.rn.f16.f32 l, %1; cvt.rn.f16.f32 h, %2; "
        "mov.b32 %0, {l, h}; }" : "=r"(r) : "f"(lo), "f"(hi));
    return r;
}

__device__ __forceinline__ void mma_f16(float* c,
    unsigned a0, unsigned a1, unsigned a2, unsigned a3,
    unsigned b0, unsigned b1)
{
    asm volatile(
        "mma.sync.aligned.m16n8k16.row.col.f32.f16.f16.f32 "
        "{%0,%1,%2,%3}, {%4,%5,%6,%7}, {%8,%9}, {%0,%1,%2,%3};"
        : "+f"(c[0]), "+f"(c[1]), "+f"(c[2]), "+f"(c[3])
        : "r"(a0), "r"(a1), "r"(a2), "r"(a3), "r"(b0), "r"(b1));
}

__device__ __forceinline__ uint32_t smem_u32(const void* p) {
    uint32_t a;
    asm("{ .reg .u64 t; cvta.to.shared.u64 t, %1; cvt.u32.u64 %0, t; }"
        : "=r"(a) : "l"(p));
    return a;
}
#define CP_ASYNC16(dst, src) \
    asm volatile("cp.async.cg.shared.global [%0], [%1], 16;" \
                 :: "r"(dst), "l"(src))
#define CP_COMMIT() asm volatile("cp.async.commit_group;" ::: "memory")
#define CP_WAIT1()  asm volatile("cp.async.wait_group 1;" ::: "memory")
#define CP_WAIT0()  asm volatile("cp.async.wait_group 0;" ::: "memory")

// ---------------------------------------------------------------------------
// Prepass W: w_body[oc48][ic96][tap9] -> g_wph[chunk][tap][icp][oc] (half2)
// ---------------------------------------------------------------------------
__global__ void prep_w_kernel(const float* __restrict__ w)
{
    int i = blockIdx.x * 256 + threadIdx.x;
    if (i >= 6 * 9 * 8 * 48) return;
    int chunk = i / 3456;
    int r  = i % 3456;
    int tap = r / 384;
    int r2  = r % 384;
    int icp = r2 / 48;
    int oc  = r2 % 48;
    int ic  = chunk * 16 + icp * 2;
    g_wph[i] = pack_h2(w[(oc * 96 + ic) * 9 + tap],
                       w[(oc * 96 + ic + 1) * 9 + tap]);
}

// ---------------------------------------------------------------------------
// Prepass X: x[b][ic][h][w] fp32 -> g_xh padded half2. One uint4 per thread.
// ---------------------------------------------------------------------------
#define PX_N (B_ * 48 * XPR * (XPC / 4))
__global__ void prep_x_kernel(const float* __restrict__ x)
{
    int i = blockIdx.x * 256 + threadIdx.x;
    if (i >= PX_N) return;
    int pc0 = (i % (XPC / 4)) * 4;
    int t   = i / (XPC / 4);
    int pr  = t % XPR;
    int t2  = t / XPR;
    int icp = t2 % 48;
    int b   = t2 / 48;
    int gr  = pr - 1;
    const float* s0 = x + ((size_t)((b * CIN + icp * 2) * HH + gr)) * WW;
    const float* s1 = s0 + (size_t)HH * WW;
    bool rok = ((unsigned)gr < (unsigned)HH);
    unsigned res[4];
    #pragma unroll
    for (int j = 0; j < 4; j++) {
        int w = pc0 + j - 1;
        bool ok = rok && ((unsigned)w < (unsigned)WW);
        float f0 = ok ? s0[w] : 0.f;
        float f1 = ok ? s1[w] : 0.f;
        res[j] = pack_h2(f0, f1);
    }
    *(uint4*)&g_xh[((size_t)(b * 48 + icp) * XPR + pr) * XPC + pc0] =
        *(uint4*)res;
}

// ---------------------------------------------------------------------------
// conv1 via mma.sync fp16 m16n8k16, cp.async double-buffered pipeline.
// CTA: 256 thr / 8 warps. Tile: 512 pixels (4 rows x 128 cols) x 48 oc.
// K = 6 chunks (16 ic as 8 half2-pairs) x 9 taps.
// Dynamic smem: xs[2][8][6][132] + wsm[2][9][8][56] = 82944 B.
// ---------------------------------------------------------------------------
#define XS_WORDS (8 * 6 * 132)   // 6336
#define WS_WORDS (9 * 8 * 56)    // 4032
#define SMEM_SZ  ((2 * XS_WORDS + 2 * WS_WORDS) * 4)

__global__ __launch_bounds__(256) void conv1_mma_kernel()
{
    extern __shared__ unsigned sm[];
    unsigned* xs0 = sm;                     // 2 x XS_WORDS
    unsigned* ws0 = sm + 2 * XS_WORDS;      // 2 x WS_WORDS

    const int tid  = threadIdx.x;
    const int lane = tid & 31;
    const int wid  = tid >> 5;
    const int g    = lane >> 2;   // 0..7
    const int u    = lane & 3;    // 0..3

    const int w0 = blockIdx.x * 128;
    const int h0 = blockIdx.y * 4;
    const int b  = blockIdx.z;

    const int wrow  = wid >> 1;
    const int wcolb = (wid & 1) * 64;

    const uint32_t xs_sm = smem_u32(xs0);
    const uint32_t ws_sm = smem_u32(ws0);

    // -------- async stage issue for one chunk --------
    auto issue = [&](int chunk, int buf) {
        // x: icp = wid; 6 rows x 33 uint4 per icp
        const unsigned* srcp =
            g_xh + ((size_t)(b * 48 + chunk * 8 + wid) * XPR + h0) * XPC + w0;
        uint32_t xd = xs_sm + (buf * XS_WORDS + wid * (6 * 132)) * 4;
        for (int j = lane; j < 198; j += 32) {
            int r = j / 33, q = j - r * 33;
            CP_ASYNC16(xd + (r * 132 + q * 4) * 4,
                       srcp + (size_t)r * XPC + q * 4);
        }
        // w: 72 rows x 12 uint4; warp wid handles rows wid*9..wid*9+8
        const unsigned* wsrc = g_wph + chunk * 3456;
        uint32_t wd = ws_sm + buf * WS_WORDS * 4;
        for (int j = lane; j < 108; j += 32) {
            int rr = wid * 9 + j / 12, q = j % 12;
            CP_ASYNC16(wd + (rr * 56 + q * 4) * 4, wsrc + rr * 48 + q * 4);
        }
    };

    float acc[4][6][4];
    #pragma unroll
    for (int t = 0; t < 4; t++)
        #pragma unroll
        for (int n = 0; n < 6; n++)
            #pragma unroll
            for (int k = 0; k < 4; k++)
                acc[t][n][k] = 0.f;

    issue(0, 0);
    CP_COMMIT();

    for (int chunk = 0; chunk < 6; chunk++) {
        const int buf = chunk & 1;
        if (chunk < 5) {
            issue(chunk + 1, buf ^ 1);
            CP_COMMIT();
            CP_WAIT1();
        } else {
            CP_WAIT0();
        }
        __syncthreads();

        const unsigned* xsb = xs0 + buf * XS_WORDS;
        const unsigned* wsb = ws0 + buf * WS_WORDS;

        #pragma unroll
        for (int tap = 0; tap < 9; tap++) {
            const int kh = tap / 3, kw = tap % 3;
            const int xr = wrow + kh;

            unsigned bf[6][2];
            #pragma unroll
            for (int n = 0; n < 6; n++) {
                bf[n][0] = wsb[(tap * 8 + u) * 56 + n * 8 + g];
                bf[n][1] = wsb[(tap * 8 + u + 4) * 56 + n * 8 + g];
            }
            #pragma unroll
            for (int t = 0; t < 4; t++) {
                const int colc = wcolb + t * 16 + g + kw;
                unsigned a0 = xsb[(u * 6 + xr) * 132 + colc];
                unsigned a1 = xsb[(u * 6 + xr) * 132 + colc + 8];
                unsigned a2 = xsb[((u + 4) * 6 + xr) * 132 + colc];
                unsigned a3 = xsb[((u + 4) * 6 + xr) * 132 + colc + 8];
                #pragma unroll
                for (int n = 0; n < 6; n++)
                    mma_f16(acc[t][n], a0, a1, a2, a3, bf[n][0], bf[n][1]);
            }
        }
        __syncthreads();
    }

    // ---- store D ----
    #pragma unroll
    for (int t = 0; t < 4; t++) {
        const int p0 = wid * 64 + t * 16 + g;
        const int h  = h0 + (p0 >> 7);
        const int wc = w0 + (p0 & 127);
        #pragma unroll
        for (int n = 0; n < 6; n++) {
            const int oc = n * 8 + 2 * u;
            float* base = g_y + ((size_t)(b * CMID + oc) * HH + h) * WW + wc;
            base[0]           = acc[t][n][0];
            base[HH * WW]     = acc[t][n][1];
            base[8]           = acc[t][n][2];
            base[HH * WW + 8] = acc[t][n][3];
        }
    }
}

// ---------------------------------------------------------------------------
// Kernel B: fused pixel_unshuffle + mask interleave + grouped 3x3 conv.
// (unchanged; ~74us)
// ---------------------------------------------------------------------------
__global__ __launch_bounds__(256) void conv2_kernel(
    const float* __restrict__ mask, const float* __restrict__ wp,
    float* __restrict__ out)
{
    __shared__ __align__(16) float sy[2][10][132];
    __shared__ __align__(16) float smm[2][10][132];
    __shared__ float swp[36];

    const int tid = threadIdx.x;
    const int hb  = blockIdx.x * 8;
    const int gp  = blockIdx.y;
    const int b   = blockIdx.z;
    const int c   = gp >> 1;
    const int dy  = gp & 1;
    const int g0  = 4 * c + 2 * dy;

    if (tid < 36) swp[tid] = wp[g0 * 18 + tid];

    for (int idx = tid; idx < 10 * 128; idx += 256) {
        int r = idx >> 7;
        int q = idx & 127;
        int gy = 2 * (hb - 1 + r) + dy;
        float2 yv = make_float2(0.f, 0.f);
        float2 mv = make_float2(0.f, 0.f);
        if ((unsigned)gy < (unsigned)HH) {
            yv = *(const float2*)&g_y[(((b * CMID + c) * HH + gy) * WW) + 2 * q];
            mv = *(const float2*)&mask[((b * HH + gy) * WW) + 2 * q];
        }
        sy[0][r][1 + q] = yv.x;  sy[1][r][1 + q] = yv.y;
        smm[0][r][1 + q] = mv.x; smm[1][r][1 + q] = mv.y;
    }
    if (tid < 10) {
        sy[0][tid][0] = 0.f;   sy[1][tid][0] = 0.f;
        sy[0][tid][129] = 0.f; sy[1][tid][129] = 0.f;
        smm[0][tid][0] = 0.f;   smm[1][tid][0] = 0.f;
        smm[0][tid][129] = 0.f; smm[1][tid][129] = 0.f;
    }
    __syncthreads();

    const int hr = tid >> 5;
    const int wq = tid & 31;
    const int w0 = wq * 4;

    float a0[4] = {0.f, 0.f, 0.f, 0.f};
    float a1[4] = {0.f, 0.f, 0.f, 0.f};

    #pragma unroll
    for (int kh = 0; kh < 3; kh++) {
        int r = hr + kh;
        float4 y0a = *(const float4*)&sy[0][r][w0];
        float2 y0b = *(const float2*)&sy[0][r][w0 + 4];
        float4 y1a = *(const float4*)&sy[1][r][w0];
        float2 y1b = *(const float2*)&sy[1][r][w0 + 4];
        float4 m0a = *(const float4*)&smm[0][r][w0];
        float2 m0b = *(const float2*)&smm[0][r][w0 + 4];
        float4 m1a = *(const float4*)&smm[1][r][w0];
        float2 m1b = *(const float2*)&smm[1][r][w0 + 4];
        float yv0[6] = {y0a.x, y0a.y, y0a.z, y0a.w, y0b.x, y0b.y};
        float yv1[6] = {y1a.x, y1a.y, y1a.z, y1a.w, y1b.x, y1b.y};
        float mv0[6] = {m0a.x, m0a.y, m0a.z, m0a.w, m0b.x, m0b.y};
        float mv1[6] = {m1a.x, m1a.y, m1a.z, m1a.w, m1b.x, m1b.y};
        #pragma unroll
        for (int kw = 0; kw < 3; kw++) {
            float wy0 = swp[kh * 3 + kw];
            float wm0 = swp[9 + kh * 3 + kw];
            float wy1 = swp[18 + kh * 3 + kw];
            float wm1 = swp[27 + kh * 3 + kw];
            #pragma unroll
            for (int p = 0; p < 4; p++) {
                a0[p] = fmaf(wy0, yv0[kw + p], a0[p]);
                a0[p] = fmaf(wm0, mv0[kw + p], a0[p]);
                a1[p] = fmaf(wy1, yv1[kw + p], a1[p]);
                a1[p] = fmaf(wm1, mv1[kw + p], a1[p]);
            }
        }
    }

    const int h = hb + hr;
    *(float4*)&out[((b * CO + g0) * H2 + h) * W2 + w0] =
        make_float4(a0[0], a0[1], a0[2], a0[3]);
    *(float4*)&out[((b * CO + g0 + 1) * H2 + h) * W2 + w0] =
        make_float4(a1[0], a1[1], a1[2], a1[3]);
}

// ---------------------------------------------------------------------------
extern "C" void kernel_launch(void* const* d_in, const int* in_sizes, int n_in,
                              void* d_out, int out_size)
{
    const float* x      = (const float*)d_in[0];
    const float* mask   = (const float*)d_in[1];
    const float* w_body = (const float*)d_in[2];
    const float* w_proj = (const float*)d_in[3];
    float* out = (float*)d_out;

    cudaFuncSetAttribute(conv1_mma_kernel,
                         cudaFuncAttributeMaxDynamicSharedMemorySize, SMEM_SZ);

    prep_w_kernel<<<(6 * 9 * 8 * 48 + 255) / 256, 256>>>(w_body);
    prep_x_kernel<<<(PX_N + 255) / 256, 256>>>(x);

    dim3 g1(WW / 128, HH / 4, B_);      // (2, 64, 8) = 1024 CTAs
    conv1_mma_kernel<<<g1, 256, SMEM_SZ>>>();

    dim3 g2(H2 / 8, 96, B_);            // (16, 96, 8)
    conv2_kernel<<<g2, 256>>>(mask, w_proj, out);
}

// round 7
// speedup vs baseline: 8.8361x; 1.0938x over previous
#include <cuda_runtime.h>
#include <cstdint>

#define B_   8
#define CIN  96
#define CMID 48
#define HH   256
#define WW   256
#define H2   128
#define W2   128
#define CO   192

// conv1 output y in fp16: [b][oc][h][w], stored as half2 (adjacent pixels). 50 MB.
__device__ unsigned g_yh[B_ * CMID * HH * WW / 2];
// Pre-packed fp16 weights: [chunk6][tap9][icp8][oc48] half2 (lo = even ic)
__device__ unsigned g_wph[6 * 9 * 8 * 48];
// Pre-packed, pre-padded fp16 x: [b][icp48][row 258][col 264] half2. ~105 MB.
#define XPR 258
#define XPC 264
__device__ unsigned g_xh[B_ * 48 * XPR * XPC];

__device__ __forceinline__ unsigned pack_h2(float lo, float hi) {
    unsigned r;
    asm("{ .reg .b16 l, h; cvt.rn.f16.f32 l, %1; cvt.rn.f16.f32 h, %2; "
        "mov.b32 %0, {l, h}; }" : "=r"(r) : "f"(lo), "f"(hi));
    return r;
}
__device__ __forceinline__ float2 h2f2(unsigned h) {
    float2 f;
    asm("{ .reg .b16 l, h; mov.b32 {l, h}, %2; "
        "cvt.f32.f16 %0, l; cvt.f32.f16 %1, h; }"
        : "=f"(f.x), "=f"(f.y) : "r"(h));
    return f;
}

__device__ __forceinline__ void mma_f16(float* c,
    unsigned a0, unsigned a1, unsigned a2, unsigned a3,
    unsigned b0, unsigned b1)
{
    asm volatile(
        "mma.sync.aligned.m16n8k16.row.col.f32.f16.f16.f32 "
        "{%0,%1,%2,%3}, {%4,%5,%6,%7}, {%8,%9}, {%0,%1,%2,%3};"
        : "+f"(c[0]), "+f"(c[1]), "+f"(c[2]), "+f"(c[3])
        : "r"(a0), "r"(a1), "r"(a2), "r"(a3), "r"(b0), "r"(b1));
}

__device__ __forceinline__ uint32_t smem_u32(const void* p) {
    uint32_t a;
    asm("{ .reg .u64 t; cvta.to.shared.u64 t, %1; cvt.u32.u64 %0, t; }"
        : "=r"(a) : "l"(p));
    return a;
}
#define CP_ASYNC16(dst, src) \
    asm volatile("cp.async.cg.shared.global [%0], [%1], 16;" \
                 :: "r"(dst), "l"(src))
#define CP_COMMIT() asm volatile("cp.async.commit_group;" ::: "memory")
#define CP_WAIT1()  asm volatile("cp.async.wait_group 1;" ::: "memory")
#define CP_WAIT0()  asm volatile("cp.async.wait_group 0;" ::: "memory")

// ---------------------------------------------------------------------------
// Prepass W: w_body[oc48][ic96][tap9] -> g_wph[chunk][tap][icp][oc] (half2)
// ---------------------------------------------------------------------------
__global__ void prep_w_kernel(const float* __restrict__ w)
{
    int i = blockIdx.x * 256 + threadIdx.x;
    if (i >= 6 * 9 * 8 * 48) return;
    int chunk = i / 3456;
    int r  = i % 3456;
    int tap = r / 384;
    int r2  = r % 384;
    int icp = r2 / 48;
    int oc  = r2 % 48;
    int ic  = chunk * 16 + icp * 2;
    g_wph[i] = pack_h2(w[(oc * 96 + ic) * 9 + tap],
                       w[(oc * 96 + ic + 1) * 9 + tap]);
}

// ---------------------------------------------------------------------------
// Prepass X: x[b][ic][h][w] fp32 -> g_xh padded half2. One uint4 per thread.
// ---------------------------------------------------------------------------
#define PX_N (B_ * 48 * XPR * (XPC / 4))
__global__ void prep_x_kernel(const float* __restrict__ x)
{
    int i = blockIdx.x * 256 + threadIdx.x;
    if (i >= PX_N) return;
    int pc0 = (i % (XPC / 4)) * 4;
    int t   = i / (XPC / 4);
    int pr  = t % XPR;
    int t2  = t / XPR;
    int icp = t2 % 48;
    int b   = t2 / 48;
    int gr  = pr - 1;
    const float* s0 = x + ((size_t)((b * CIN + icp * 2) * HH + gr)) * WW;
    const float* s1 = s0 + (size_t)HH * WW;
    bool rok = ((unsigned)gr < (unsigned)HH);
    unsigned res[4];
    #pragma unroll
    for (int j = 0; j < 4; j++) {
        int w = pc0 + j - 1;
        bool ok = rok && ((unsigned)w < (unsigned)WW);
        float f0 = ok ? s0[w] : 0.f;
        float f1 = ok ? s1[w] : 0.f;
        res[j] = pack_h2(f0, f1);
    }
    *(uint4*)&g_xh[((size_t)(b * 48 + icp) * XPR + pr) * XPC + pc0] =
        *(uint4*)res;
}

// ---------------------------------------------------------------------------
// conv1 via mma.sync fp16 m16n8k16, cp.async double-buffered pipeline.
// CTA: 256 thr / 8 warps. Tile: 512 pixels (4 rows x 128 cols) x 48 oc.
// Epilogue packs fp16 y via shfl.xor(4) (lanes g / g^1 hold adjacent pixels).
// ---------------------------------------------------------------------------
#define XS_WORDS (8 * 6 * 132)   // 6336
#define WS_WORDS (9 * 8 * 56)    // 4032
#define SMEM_SZ  ((2 * XS_WORDS + 2 * WS_WORDS) * 4)

__global__ __launch_bounds__(256) void conv1_mma_kernel()
{
    extern __shared__ unsigned sm[];
    unsigned* xs0 = sm;                     // 2 x XS_WORDS
    unsigned* ws0 = sm + 2 * XS_WORDS;      // 2 x WS_WORDS

    const int tid  = threadIdx.x;
    const int lane = tid & 31;
    const int wid  = tid >> 5;
    const int g    = lane >> 2;   // 0..7
    const int u    = lane & 3;    // 0..3

    const int w0 = blockIdx.x * 128;
    const int h0 = blockIdx.y * 4;
    const int b  = blockIdx.z;

    const int wrow  = wid >> 1;
    const int wcolb = (wid & 1) * 64;

    const uint32_t xs_sm = smem_u32(xs0);
    const uint32_t ws_sm = smem_u32(ws0);

    auto issue = [&](int chunk, int buf) {
        const unsigned* srcp =
            g_xh + ((size_t)(b * 48 + chunk * 8 + wid) * XPR + h0) * XPC + w0;
        uint32_t xd = xs_sm + (buf * XS_WORDS + wid * (6 * 132)) * 4;
        for (int j = lane; j < 198; j += 32) {
            int r = j / 33, q = j - r * 33;
            CP_ASYNC16(xd + (r * 132 + q * 4) * 4,
                       srcp + (size_t)r * XPC + q * 4);
        }
        const unsigned* wsrc = g_wph + chunk * 3456;
        uint32_t wd = ws_sm + buf * WS_WORDS * 4;
        for (int j = lane; j < 108; j += 32) {
            int rr = wid * 9 + j / 12, q = j % 12;
            CP_ASYNC16(wd + (rr * 56 + q * 4) * 4, wsrc + rr * 48 + q * 4);
        }
    };

    float acc[4][6][4];
    #pragma unroll
    for (int t = 0; t < 4; t++)
        #pragma unroll
        for (int n = 0; n < 6; n++)
            #pragma unroll
            for (int k = 0; k < 4; k++)
                acc[t][n][k] = 0.f;

    issue(0, 0);
    CP_COMMIT();

    for (int chunk = 0; chunk < 6; chunk++) {
        const int buf = chunk & 1;
        if (chunk < 5) {
            issue(chunk + 1, buf ^ 1);
            CP_COMMIT();
            CP_WAIT1();
        } else {
            CP_WAIT0();
        }
        __syncthreads();

        const unsigned* xsb = xs0 + buf * XS_WORDS;
        const unsigned* wsb = ws0 + buf * WS_WORDS;

        #pragma unroll
        for (int tap = 0; tap < 9; tap++) {
            const int kh = tap / 3, kw = tap % 3;
            const int xr = wrow + kh;

            unsigned bf[6][2];
            #pragma unroll
            for (int n = 0; n < 6; n++) {
                bf[n][0] = wsb[(tap * 8 + u) * 56 + n * 8 + g];
                bf[n][1] = wsb[(tap * 8 + u + 4) * 56 + n * 8 + g];
            }
            #pragma unroll
            for (int t = 0; t < 4; t++) {
                const int colc = wcolb + t * 16 + g + kw;
                unsigned a0 = xsb[(u * 6 + xr) * 132 + colc];
                unsigned a1 = xsb[(u * 6 + xr) * 132 + colc + 8];
                unsigned a2 = xsb[((u + 4) * 6 + xr) * 132 + colc];
                unsigned a3 = xsb[((u + 4) * 6 + xr) * 132 + colc + 8];
                #pragma unroll
                for (int n = 0; n < 6; n++)
                    mma_f16(acc[t][n], a0, a1, a2, a3, bf[n][0], bf[n][1]);
            }
        }
        __syncthreads();
    }

    // ---- store D as fp16 half2 (pair lanes g, g^1 = adjacent pixels) ----
    #pragma unroll
    for (int t = 0; t < 4; t++) {
        const int p0 = wid * 64 + t * 16 + g;         // even iff g even
        const int h  = h0 + (p0 >> 7);
        const int hc = ((w0 + (p0 & 127)) >> 1);      // half2 col index
        #pragma unroll
        for (int n = 0; n < 6; n++) {
            const int oc = n * 8 + 2 * u;
            float q0 = __shfl_xor_sync(0xffffffffu, acc[t][n][0], 4);
            float q1 = __shfl_xor_sync(0xffffffffu, acc[t][n][1], 4);
            float q2 = __shfl_xor_sync(0xffffffffu, acc[t][n][2], 4);
            float q3 = __shfl_xor_sync(0xffffffffu, acc[t][n][3], 4);
            if (!(g & 1)) {
                unsigned* base =
                    g_yh + ((size_t)(b * CMID + oc) * HH + h) * 128 + hc;
                base[0]                    = pack_h2(acc[t][n][0], q0);
                base[(size_t)HH * WW / 2]  = pack_h2(acc[t][n][1], q1);
                base[4]                    = pack_h2(acc[t][n][2], q2);
                base[(size_t)HH * WW / 2 + 4] = pack_h2(acc[t][n][3], q3);
            }
        }
    }
}

// ---------------------------------------------------------------------------
// Kernel B: fused pixel_unshuffle + mask interleave + grouped 3x3 conv.
// CTA tile: 16 rows x 128 cols, thread = 2 rows x 4 cols, y read as fp16.
// ---------------------------------------------------------------------------
__global__ __launch_bounds__(256) void conv2_kernel(
    const float* __restrict__ mask, const float* __restrict__ wp,
    float* __restrict__ out)
{
    __shared__ __align__(16) float sy[2][18][132];
    __shared__ __align__(16) float smm[2][18][132];
    __shared__ float swp[36];

    const int tid = threadIdx.x;
    const int hb  = blockIdx.x * 16;
    const int gp  = blockIdx.y;     // (c, dy)
    const int b   = blockIdx.z;
    const int c   = gp >> 1;
    const int dy  = gp & 1;
    const int g0  = 4 * c + 2 * dy;

    if (tid < 36) swp[tid] = wp[g0 * 18 + tid];

    // stage 18 rows x 128 q; thread handles 2 q per slot (uint2 y, float4 mask)
    #pragma unroll
    for (int it = 0; it < 5; it++) {
        int idx = it * 256 + tid;
        if (idx < 1152) {
            int r  = idx >> 6;
            int q2 = (idx & 63) * 2;
            int gy = 2 * (hb - 1 + r) + dy;
            uint2 yv = make_uint2(0u, 0u);
            float4 mv = make_float4(0.f, 0.f, 0.f, 0.f);
            if ((unsigned)gy < (unsigned)HH) {
                yv = *(const uint2*)&g_yh[((size_t)(b * CMID + c) * HH + gy) * 128 + q2];
                mv = *(const float4*)&mask[((size_t)(b * HH) + gy) * WW + 2 * q2];
            }
            float2 f0 = h2f2(yv.x), f1 = h2f2(yv.y);
            sy[0][r][1 + q2] = f0.x;  sy[1][r][1 + q2] = f0.y;
            sy[0][r][2 + q2] = f1.x;  sy[1][r][2 + q2] = f1.y;
            smm[0][r][1 + q2] = mv.x; smm[1][r][1 + q2] = mv.y;
            smm[0][r][2 + q2] = mv.z; smm[1][r][2 + q2] = mv.w;
        }
    }
    if (tid < 18) {
        sy[0][tid][0] = 0.f;   sy[1][tid][0] = 0.f;
        sy[0][tid][129] = 0.f; sy[1][tid][129] = 0.f;
        smm[0][tid][0] = 0.f;   smm[1][tid][0] = 0.f;
        smm[0][tid][129] = 0.f; smm[1][tid][129] = 0.f;
    }
    __syncthreads();

    const int rr  = tid >> 5;        // output rows 2rr, 2rr+1
    const int w0c = (tid & 31) * 4;

    float a[2][2][4];
    #pragma unroll
    for (int o = 0; o < 2; o++)
        #pragma unroll
        for (int gx = 0; gx < 2; gx++)
            #pragma unroll
            for (int p = 0; p < 4; p++)
                a[o][gx][p] = 0.f;

    #pragma unroll
    for (int r = 0; r < 4; r++) {
        const int sr = 2 * rr + r;
        float4 ya0 = *(const float4*)&sy[0][sr][w0c];
        float2 yb0 = *(const float2*)&sy[0][sr][w0c + 4];
        float4 ya1 = *(const float4*)&sy[1][sr][w0c];
        float2 yb1 = *(const float2*)&sy[1][sr][w0c + 4];
        float4 ma0 = *(const float4*)&smm[0][sr][w0c];
        float2 mb0 = *(const float2*)&smm[0][sr][w0c + 4];
        float4 ma1 = *(const float4*)&smm[1][sr][w0c];
        float2 mb1 = *(const float2*)&smm[1][sr][w0c + 4];
        float yv0[6] = {ya0.x, ya0.y, ya0.z, ya0.w, yb0.x, yb0.y};
        float yv1[6] = {ya1.x, ya1.y, ya1.z, ya1.w, yb1.x, yb1.y};
        float mv0[6] = {ma0.x, ma0.y, ma0.z, ma0.w, mb0.x, mb0.y};
        float mv1[6] = {ma1.x, ma1.y, ma1.z, ma1.w, mb1.x, mb1.y};

        #pragma unroll
        for (int orow = 0; orow < 2; orow++) {
            const int kh = r - orow;
            if (kh < 0 || kh > 2) continue;
            #pragma unroll
            for (int kw = 0; kw < 3; kw++) {
                float wy0 = swp[kh * 3 + kw];
                float wm0 = swp[9 + kh * 3 + kw];
                float wy1 = swp[18 + kh * 3 + kw];
                float wm1 = swp[27 + kh * 3 + kw];
                #pragma unroll
                for (int p = 0; p < 4; p++) {
                    a[orow][0][p] = fmaf(wy0, yv0[kw + p], a[orow][0][p]);
                    a[orow][0][p] = fmaf(wm0, mv0[kw + p], a[orow][0][p]);
                    a[orow][1][p] = fmaf(wy1, yv1[kw + p], a[orow][1][p]);
                    a[orow][1][p] = fmaf(wm1, mv1[kw + p], a[orow][1][p]);
                }
            }
        }
    }

    #pragma unroll
    for (int orow = 0; orow < 2; orow++) {
        const int h = hb + 2 * rr + orow;
        *(float4*)&out[((size_t)(b * CO + g0) * H2 + h) * W2 + w0c] =
            make_float4(a[orow][0][0], a[orow][0][1], a[orow][0][2], a[orow][0][3]);
        *(float4*)&out[((size_t)(b * CO + g0 + 1) * H2 + h) * W2 + w0c] =
            make_float4(a[orow][1][0], a[orow][1][1], a[orow][1][2], a[orow][1][3]);
    }
}

// ---------------------------------------------------------------------------
extern "C" void kernel_launch(void* const* d_in, const int* in_sizes, int n_in,
                              void* d_out, int out_size)
{
    const float* x      = (const float*)d_in[0];
    const float* mask   = (const float*)d_in[1];
    const float* w_body = (const float*)d_in[2];
    const float* w_proj = (const float*)d_in[3];
    float* out = (float*)d_out;

    cudaFuncSetAttribute(conv1_mma_kernel,
                         cudaFuncAttributeMaxDynamicSharedMemorySize, SMEM_SZ);

    prep_w_kernel<<<(6 * 9 * 8 * 48 + 255) / 256, 256>>>(w_body);
    prep_x_kernel<<<(PX_N + 255) / 256, 256>>>(x);

    dim3 g1(WW / 128, HH / 4, B_);      // (2, 64, 8) = 1024 CTAs
    conv1_mma_kernel<<<g1, 256, SMEM_SZ>>>();

    dim3 g2(H2 / 16, 96, B_);           // (8, 96, 8) = 6144 CTAs
    conv2_kernel<<<g2, 256>>>(mask, w_proj, out);
}